// round 5
// baseline (speedup 1.0000x reference)
#include <cuda_runtime.h>

// SymmetryConstraint: warp-per-batch closed-form moment reduction.
// Per (batch, class k in {0,1,2}) with m points, u = x-0.5:
//   pair-loss sum = (m-2)*Su2 + Su^2 + m*Sy2 - Sy^2
//   pair count    = m(m-1)/2
// result = total_loss / max(total_count, 1)

#define BATCH   256
#define NPTS    512
#define WARPS   4
#define THREADS (WARPS * 32)
#define BLOCKS  (BATCH / WARPS)   // 64

__device__ float2       g_partial[BLOCKS];   // (loss, count) per block
__device__ unsigned int g_done = 0u;

__global__ __launch_bounds__(THREADS)
void symmetry_kernel(const float4* __restrict__ kp4,
                     const int2*   __restrict__ cls2,
                     float* __restrict__ out)
{
    const int tid  = threadIdx.x;
    const int lane = tid & 31;
    const int wid  = tid >> 5;
    const int b    = blockIdx.x * WARPS + wid;   // warp-per-batch

    // 256 float4 (coords, 2 pts each) and 256 int2 (classes, 2 pts each) per batch
    const float4* kb = kp4  + (size_t)b * (NPTS / 2);
    const int2*   cb = cls2 + (size_t)b * (NPTS / 2);

    // float moments: 3 classes x {Su, Su2, Sy, Sy2}; integer counts on ALU pipe
    float fa[12];
#pragma unroll
    for (int i = 0; i < 12; i++) fa[i] = 0.f;
    int m0 = 0, m1 = 0, m2 = 0;

#pragma unroll
    for (int j = 0; j < 8; j++) {
        const int e = lane + 32 * j;          // coalesced across lanes
        float4 p = kb[e];
        int2   c = cb[e];

        float ux[2] = { p.x - 0.5f, p.z - 0.5f };
        float yy[2] = { p.y,        p.w        };
        int   cc[2] = { c.x,        c.y        };

#pragma unroll
        for (int t = 0; t < 2; t++) {
            float u = ux[t], y = yy[t];
            int ci = cc[t];
            m0 += (ci == 0);
            m1 += (ci == 1);
            m2 += (ci == 2);
#pragma unroll
            for (int k = 0; k < 3; k++) {
                float w = (ci == k) ? 1.f : 0.f;
                fa[k * 4 + 0] += w * u;
                fa[k * 4 + 1] += w * u * u;
                fa[k * 4 + 2] += w * y;
                fa[k * 4 + 3] += w * y * y;
            }
        }
    }

    // warp reduce (independent values pipeline across the 5 stages)
#pragma unroll
    for (int off = 16; off; off >>= 1) {
#pragma unroll
        for (int i = 0; i < 12; i++)
            fa[i] += __shfl_down_sync(0xffffffffu, fa[i], off);
        m0 += __shfl_down_sync(0xffffffffu, m0, off);
        m1 += __shfl_down_sync(0xffffffffu, m1, off);
        m2 += __shfl_down_sync(0xffffffffu, m2, off);
    }

    __shared__ float2 s_wp[WARPS];
    __shared__ int    s_last;

    if (lane == 0) {
        float mk[3] = { (float)m0, (float)m1, (float)m2 };
        float loss = 0.f, cnt = 0.f;
#pragma unroll
        for (int k = 0; k < 3; k++) {
            float m   = mk[k];
            float su  = fa[k * 4 + 0];
            float su2 = fa[k * 4 + 1];
            float sy  = fa[k * 4 + 2];
            float sy2 = fa[k * 4 + 3];
            loss += (m - 2.f) * su2 + su * su + m * sy2 - sy * sy;
            cnt  += 0.5f * m * (m - 1.f);
        }
        s_wp[wid] = make_float2(loss, cnt);
    }
    __syncthreads();

    if (tid == 0) {
        float L = 0.f, C = 0.f;
#pragma unroll
        for (int w = 0; w < WARPS; w++) { L += s_wp[w].x; C += s_wp[w].y; }
        g_partial[blockIdx.x] = make_float2(L, C);
        __threadfence();
        unsigned int prev = atomicAdd(&g_done, 1u);
        s_last = (prev == BLOCKS - 1) ? 1 : 0;
    }
    __syncthreads();

    if (s_last && wid == 0) {
        // last block, warp 0: reduce 64 partials (deterministic order)
        const volatile float2* gp = (const volatile float2*)g_partial;
        float2 a = { gp[lane].x,      gp[lane].y      };
        float2 c = { gp[lane + 32].x, gp[lane + 32].y };
        float L = a.x + c.x;
        float C = a.y + c.y;
#pragma unroll
        for (int off = 16; off; off >>= 1) {
            L += __shfl_down_sync(0xffffffffu, L, off);
            C += __shfl_down_sync(0xffffffffu, C, off);
        }
        if (lane == 0) {
            out[0] = L / fmaxf(C, 1.f);
            g_done = 0u;   // reset for next graph replay
        }
    }
}

extern "C" void kernel_launch(void* const* d_in, const int* in_sizes, int n_in,
                              void* d_out, int out_size)
{
    const float4* kp4  = (const float4*)d_in[0];  // [256, 512, 2] f32
    const int2*   cls2 = (const int2*)d_in[1];    // [256, 512] i32
    float*        out  = (float*)d_out;           // [1] f32
    symmetry_kernel<<<BLOCKS, THREADS>>>(kp4, cls2, out);
}

// round 8
// speedup vs baseline: 1.0257x; 1.0257x over previous
#include <cuda_runtime.h>

// SymmetryConstraint: block-per-batch closed-form moment reduction,
// deterministic fixed-point global accumulation.
// Per (batch, class k in {0,1,2}) with m points, u = x-0.5:
//   pair-loss sum = (m-2)*Su2 + Su^2 + m*Sy2 - Sy^2   (>= 0)
//   pair count    = m(m-1)/2
// result = total_loss / max(total_count, 1)

#define BATCH   256
#define NPTS    512
#define THREADS 256
#define NWARP   (THREADS / 32)

__device__ unsigned long long g_loss_fix = 0ULL;
__device__ unsigned long long g_cnt_fix  = 0ULL;
__device__ unsigned int       g_done     = 0u;

#define LOSS_SCALE 33554432.0f   // 2^25

__global__ __launch_bounds__(THREADS)
void symmetry_kernel(const float4* __restrict__ kp4,
                     const int2*   __restrict__ cls2,
                     float* __restrict__ out)
{
    const int b    = blockIdx.x;
    const int tid  = threadIdx.x;
    const int lane = tid & 31;
    const int wid  = tid >> 5;

    // 256 float4 (2 pts each) + 256 int2 per batch; 1 of each per thread.
    float4 p = kp4 [(size_t)b * (NPTS / 2) + tid];
    int2   c = cls2[(size_t)b * (NPTS / 2) + tid];

    // 3 classes x {Su, Su2, Sy, Sy2} in float; counts in int.
    float fa[12];
#pragma unroll
    for (int i = 0; i < 12; i++) fa[i] = 0.f;
    int m0 = 0, m1 = 0, m2 = 0;

    float ux[2] = { p.x - 0.5f, p.z - 0.5f };
    float yy[2] = { p.y,        p.w        };
    int   cc[2] = { c.x,        c.y        };

#pragma unroll
    for (int t = 0; t < 2; t++) {
        float u = ux[t], y = yy[t];
        int ci = cc[t];
        m0 += (ci == 0);
        m1 += (ci == 1);
        m2 += (ci == 2);
#pragma unroll
        for (int k = 0; k < 3; k++) {
            float w = (ci == k) ? 1.f : 0.f;
            fa[k * 4 + 0] += w * u;
            fa[k * 4 + 1] += w * u * u;
            fa[k * 4 + 2] += w * y;
            fa[k * 4 + 3] += w * y * y;
        }
    }

    // warp reduce: 12 floats via shuffles (independent -> pipelined),
    // 3 ints via single REDUX each.
#pragma unroll
    for (int off = 16; off; off >>= 1) {
#pragma unroll
        for (int i = 0; i < 12; i++)
            fa[i] += __shfl_down_sync(0xffffffffu, fa[i], off);
    }
    m0 = __reduce_add_sync(0xffffffffu, m0);
    m1 = __reduce_add_sync(0xffffffffu, m1);
    m2 = __reduce_add_sync(0xffffffffu, m2);

    // per-warp results -> smem: 15 floats per warp (12 moments + 3 counts)
    __shared__ float s_mom[NWARP][16];   // padded row
    if (lane == 0) {
#pragma unroll
        for (int i = 0; i < 12; i++) s_mom[wid][i] = fa[i];
        s_mom[wid][12] = (float)m0;
        s_mom[wid][13] = (float)m1;
        s_mom[wid][14] = (float)m2;
    }
    __syncthreads();

    if (wid == 0) {
        // lanes 0..14 each sum one quantity across the 8 warps (parallel)
        float s = 0.f;
        if (lane < 15) {
#pragma unroll
            for (int w = 0; w < NWARP; w++) s += s_mom[w][lane];
        }
        // gather all 15 totals to every lane via pipelined shuffles
        float tot[15];
#pragma unroll
        for (int i = 0; i < 15; i++)
            tot[i] = __shfl_sync(0xffffffffu, s, i);

        if (lane == 0) {
            float loss = 0.f, cnt = 0.f;
#pragma unroll
            for (int k = 0; k < 3; k++) {
                float su  = tot[k * 4 + 0];
                float su2 = tot[k * 4 + 1];
                float sy  = tot[k * 4 + 2];
                float sy2 = tot[k * 4 + 3];
                float m   = tot[12 + k];
                loss += (m - 2.f) * su2 + su * su + m * sy2 - sy * sy;
                cnt  += 0.5f * m * (m - 1.f);   // exact: m integer < 2^10
            }
            loss = fmaxf(loss, 0.f);

            // deterministic order-independent integer accumulation
            unsigned long long lfix = (unsigned long long)(loss * LOSS_SCALE + 0.5f);
            unsigned long long cfix = (unsigned long long)(cnt + 0.5f);
            atomicAdd(&g_loss_fix, lfix);
            atomicAdd(&g_cnt_fix,  cfix);
            __threadfence();

            if (atomicAdd(&g_done, 1u) == BATCH - 1) {
                unsigned long long L = atomicAdd(&g_loss_fix, 0ULL);
                unsigned long long C = atomicAdd(&g_cnt_fix,  0ULL);
                double total = (double)L * (1.0 / 33554432.0);
                double denom = (C > 0ULL) ? (double)C : 1.0;
                out[0] = (float)(total / denom);
                // reset for next graph replay
                g_loss_fix = 0ULL;
                g_cnt_fix  = 0ULL;
                g_done     = 0u;
                __threadfence();
            }
        }
    }
}

extern "C" void kernel_launch(void* const* d_in, const int* in_sizes, int n_in,
                              void* d_out, int out_size)
{
    const float4* kp4  = (const float4*)d_in[0];  // [256, 512, 2] f32
    const int2*   cls2 = (const int2*)d_in[1];    // [256, 512] i32
    float*        out  = (float*)d_out;           // [1] f32
    symmetry_kernel<<<BATCH, THREADS>>>(kp4, cls2, out);
}